// round 13
// baseline (speedup 1.0000x reference)
#include <cuda_runtime.h>

#define TOKS    2048
#define NNODES  1024
#define FEAT    128
#define QUADS   32                 // float4 per full token row
#define QB      16                 // float4 per row per block (64 features)
#define NBLK    128                // 64 chunks x 2 feature halves
#define CHUNK   32
#define THREADS 512
#define NGRP    16                 // warps per block

__device__ __forceinline__ float4 f4add(float4 a, float4 b) {
    return make_float4(a.x + b.x, a.y + b.y, a.z + b.z, a.w + b.w);
}

__global__ __launch_bounds__(THREADS, 1)
void span_encoder_kernel(const int* __restrict__ starts,
                         const int* __restrict__ ends,
                         const float4* __restrict__ embed4,
                         float4* __restrict__ out4)
{
    __shared__ int s_full[NNODES];                       //  4 KB
    __shared__ int s_part[NNODES];                       //  4 KB
    __shared__ int s_cnt;                                // nfull | npart<<16
    __shared__ __align__(16) float4 sdiff[CHUNK][QB];    //  8 KB diff array
    __shared__ __align__(16) float4 gaccs[NGRP][QB];     //  4 KB warp accums
    __shared__ __align__(16) float4 sfull[QB];           // full-cover total
    __shared__ __align__(16) float4 sred[16][QB];        //  4 KB 2-token sums
    __shared__ __align__(16) float4 ssup[4][QB];         //  1 KB 8-token sums

    const int tid  = threadIdx.x;
    const int lane = tid & 31;
    const int g    = tid >> 5;               // warp 0..15
    const int sub  = lane >> 4;              // node slot 0/1
    const int qq   = lane & 15;              // float4 lane within 64-feat row
    const int c    = blockIdx.x >> 1;
    const int h    = blockIdx.x & 1;         // feature half
    const int c0   = c * CHUNK;
    const int qoff = h * QB;                 // float4 offset into full row
    const unsigned lt_mask = (1u << lane) - 1u;
    const float4 zero4 = make_float4(0.f, 0.f, 0.f, 0.f);

    if (tid == 0) s_cnt = 0;
    ((float4*)&sdiff[0][0])[tid] = zero4;    // CHUNK*QB == 512
    __syncthreads();                         // s_cnt=0 visible BEFORE atomics

    // ---- Classify 1024 nodes (2 rounds), ballot compaction --------------
    #pragma unroll
    for (int r = 0; r < 2; ++r) {
        int n  = r * THREADS + tid;
        int s  = __ldg(&starts[n]);
        int e  = __ldg(&ends[n]);
        int lo = s - c0;     if (lo < 0)     lo = 0;
        int hi = e - c0 + 1; if (hi > CHUNK) hi = CHUNK;
        bool ov     = (lo < hi);
        bool isFull = ov && (lo == 0) && (hi == CHUNK);
        bool isPart = ov && !isFull;

        unsigned mf = __ballot_sync(0xffffffffu, isFull);
        unsigned mp = __ballot_sync(0xffffffffu, isPart);
        int base = 0;
        if (lane == 0 && (mf | mp))
            base = atomicAdd(&s_cnt, (__popc(mp) << 16) | __popc(mf));
        base = __shfl_sync(0xffffffffu, base, 0);
        if (isFull) s_full[(base & 0xffff) + __popc(mf & lt_mask)] = n;
        if (isPart) s_part[(base >> 16)   + __popc(mp & lt_mask)]
                        = (n << 12) | (lo << 6) | hi;
    }
    __syncthreads();

    const int cnt   = s_cnt;
    const int nfull = cnt & 0xffff;
    const int npart = cnt >> 16;

    // ---- Partial nodes: 1 node/warp; sub0 adds at lo, sub1 subs at hi ---
    for (int p = g; p < npart; p += NGRP) {
        int pk = s_part[p];
        int n  = pk >> 12;
        int lo = (pk >> 6) & 63;
        int hi = pk & 63;
        float4 v = __ldg(&embed4[n * QUADS + qoff + qq]);
        if (sub == 0) {
            float* d = &sdiff[lo][qq].x;
            atomicAdd(d + 0, v.x);
            atomicAdd(d + 1, v.y);
            atomicAdd(d + 2, v.z);
            atomicAdd(d + 3, v.w);
        } else if (hi < CHUNK) {
            float* d = &sdiff[hi][qq].x;
            atomicAdd(d + 0, -v.x);
            atomicAdd(d + 1, -v.y);
            atomicAdd(d + 2, -v.z);
            atomicAdd(d + 3, -v.w);
        }
    }

    // ---- Full-cover nodes: 2 nodes/warp/iter, MLP=8 then residue --------
    {
        float4 a0 = zero4, a1 = zero4, a2 = zero4, a3 = zero4;
        int i = g * 2 + sub;                 // slot 0..31, stride 32
        for (; i + 224 < nfull; i += 256) {  // 8 entries in flight per slot
            int n0 = s_full[i];
            int n1 = s_full[i +  32];
            int n2 = s_full[i +  64];
            int n3 = s_full[i +  96];
            int n4 = s_full[i + 128];
            int n5 = s_full[i + 160];
            int n6 = s_full[i + 192];
            int n7 = s_full[i + 224];
            float4 v0 = __ldg(&embed4[n0 * QUADS + qoff + qq]);
            float4 v1 = __ldg(&embed4[n1 * QUADS + qoff + qq]);
            float4 v2 = __ldg(&embed4[n2 * QUADS + qoff + qq]);
            float4 v3 = __ldg(&embed4[n3 * QUADS + qoff + qq]);
            float4 v4 = __ldg(&embed4[n4 * QUADS + qoff + qq]);
            float4 v5 = __ldg(&embed4[n5 * QUADS + qoff + qq]);
            float4 v6 = __ldg(&embed4[n6 * QUADS + qoff + qq]);
            float4 v7 = __ldg(&embed4[n7 * QUADS + qoff + qq]);
            a0 = f4add(a0, f4add(v0, v4));
            a1 = f4add(a1, f4add(v1, v5));
            a2 = f4add(a2, f4add(v2, v6));
            a3 = f4add(a3, f4add(v3, v7));
        }
        for (; i + 96 < nfull; i += 128) {   // MLP=4 residue
            int n0 = s_full[i];
            int n1 = s_full[i + 32];
            int n2 = s_full[i + 64];
            int n3 = s_full[i + 96];
            a0 = f4add(a0, __ldg(&embed4[n0 * QUADS + qoff + qq]));
            a1 = f4add(a1, __ldg(&embed4[n1 * QUADS + qoff + qq]));
            a2 = f4add(a2, __ldg(&embed4[n2 * QUADS + qoff + qq]));
            a3 = f4add(a3, __ldg(&embed4[n3 * QUADS + qoff + qq]));
        }
        for (; i < nfull; i += 32)
            a0 = f4add(a0, __ldg(&embed4[s_full[i] * QUADS + qoff + qq]));
        float4 a = f4add(f4add(a0, a1), f4add(a2, a3));
        // fold the two node slots (sub 0/1) across half-warps
        a.x += __shfl_xor_sync(0xffffffffu, a.x, 16);
        a.y += __shfl_xor_sync(0xffffffffu, a.y, 16);
        a.z += __shfl_xor_sync(0xffffffffu, a.z, 16);
        a.w += __shfl_xor_sync(0xffffffffu, a.w, 16);
        if (sub == 0) gaccs[g][qq] = a;
    }
    __syncthreads();

    // ---- Phase B: role-split warps --------------------------------------
    if (g < 8) {                             // 2-token sums: entries 2g+sub
        int sidx = 2 * g + sub;
        sred[sidx][qq] = f4add(sdiff[2 * sidx][qq], sdiff[2 * sidx + 1][qq]);
    } else if (g < 10) {                     // 8-token sums: entries 2(g-8)+sub
        int a = 2 * (g - 8) + sub;
        float4 t0 = f4add(sdiff[8 * a + 0][qq], sdiff[8 * a + 1][qq]);
        float4 t1 = f4add(sdiff[8 * a + 2][qq], sdiff[8 * a + 3][qq]);
        float4 t2 = f4add(sdiff[8 * a + 4][qq], sdiff[8 * a + 5][qq]);
        float4 t3 = f4add(sdiff[8 * a + 6][qq], sdiff[8 * a + 7][qq]);
        ssup[a][qq] = f4add(f4add(t0, t1), f4add(t2, t3));
    } else if (g == 10) {                    // full-cover total: 8-deep + fold
        float4 a = zero4;
        #pragma unroll
        for (int r = 0; r < 8; ++r)
            a = f4add(a, gaccs[8 * sub + r][qq]);
        a.x += __shfl_xor_sync(0xffffffffu, a.x, 16);
        a.y += __shfl_xor_sync(0xffffffffu, a.y, 16);
        a.z += __shfl_xor_sync(0xffffffffu, a.z, 16);
        a.w += __shfl_xor_sync(0xffffffffu, a.w, 16);
        if (sub == 0) sfull[qq] = a;
    }
    __syncthreads();

    // ---- Phase C: scan, warp g owns tokens 2g and 2g+1 ------------------
    {
        const int a = g >> 2;                // 8-token groups before token 2g
        const int b = g & 3;                 // 2-token groups in current one
        float4 acc = sfull[qq];
        #pragma unroll
        for (int ss = 0; ss < 3; ++ss)
            if (ss < a) acc = f4add(acc, ssup[ss][qq]);
        #pragma unroll
        for (int j = 0; j < 3; ++j)
            if (j < b) acc = f4add(acc, sred[4 * a + j][qq]);
        acc = f4add(acc, sdiff[2 * g][qq]);
        out4[(c0 + 2 * g) * QUADS + qoff + qq] = acc;
        acc = f4add(acc, sdiff[2 * g + 1][qq]);
        out4[(c0 + 2 * g + 1) * QUADS + qoff + qq] = acc;
    }
}

extern "C" void kernel_launch(void* const* d_in, const int* in_sizes, int n_in,
                              void* d_out, int out_size) {
    const int*    starts = (const int*)d_in[0];
    const int*    ends   = (const int*)d_in[1];
    const float4* embed  = (const float4*)d_in[2];
    float4*       out    = (float4*)d_out;
    (void)in_sizes; (void)n_in; (void)out_size;
    span_encoder_kernel<<<NBLK, THREADS>>>(starts, ends, embed, out);
}

// round 14
// speedup vs baseline: 1.0295x; 1.0295x over previous
#include <cuda_runtime.h>

#define TOKS    2048
#define NNODES  1024
#define FEAT    128
#define QUADS   32                 // float4 per full token row
#define QB      16                 // float4 per row per block (64 features)
#define NBLK    128                // 64 chunks x 2 feature halves
#define CHUNK   32
#define THREADS 512
#define NGRP    16                 // warps per block

__device__ __forceinline__ float4 f4add(float4 a, float4 b) {
    return make_float4(a.x + b.x, a.y + b.y, a.z + b.z, a.w + b.w);
}

__global__ __launch_bounds__(THREADS, 1)
void span_encoder_kernel(const int2* __restrict__ starts2,
                         const int2* __restrict__ ends2,
                         const float4* __restrict__ embed4,
                         float4* __restrict__ out4)
{
    __shared__ int s_full[NNODES];                       //  4 KB
    __shared__ int s_part[NNODES];                       //  4 KB
    __shared__ int s_cnt;                                // nfull | npart<<16
    __shared__ __align__(16) float4 sdiff[CHUNK][QB];    //  8 KB diff array
    __shared__ __align__(16) float4 gaccs[NGRP][QB];     //  4 KB warp accums
    __shared__ __align__(16) float4 sfull[QB];           // full-cover total
    __shared__ __align__(16) float4 sred[16][QB];        //  4 KB 2-token sums
    __shared__ __align__(16) float4 ssup[4][QB];         //  1 KB 8-token sums

    const int tid  = threadIdx.x;
    const int lane = tid & 31;
    const int g    = tid >> 5;               // warp 0..15
    const int sub  = lane >> 4;              // node slot 0/1
    const int qq   = lane & 15;              // float4 lane within 64-feat row
    const int c    = blockIdx.x >> 1;
    const int h    = blockIdx.x & 1;         // feature half
    const int c0   = c * CHUNK;
    const int qoff = h * QB;                 // float4 offset into full row
    const unsigned lt_mask = (1u << lane) - 1u;
    const float4 zero4 = make_float4(0.f, 0.f, 0.f, 0.f);

    // ---- Prefetch spans (vectorized) at kernel top ----------------------
    int2 sv = __ldg(&starts2[tid]);          // nodes 2*tid, 2*tid+1
    int2 ev = __ldg(&ends2[tid]);

    if (tid == 0) s_cnt = 0;
    __syncthreads();                         // s_cnt=0 visible BEFORE atomics

    // ---- Classify 2 nodes/thread, one packed atomic per warp ------------
    {
        int lo0 = sv.x - c0;     if (lo0 < 0)     lo0 = 0;
        int hi0 = ev.x - c0 + 1; if (hi0 > CHUNK) hi0 = CHUNK;
        int lo1 = sv.y - c0;     if (lo1 < 0)     lo1 = 0;
        int hi1 = ev.y - c0 + 1; if (hi1 > CHUNK) hi1 = CHUNK;
        bool ov0 = (lo0 < hi0), ov1 = (lo1 < hi1);
        bool f0  = ov0 && (lo0 == 0) && (hi0 == CHUNK);
        bool f1  = ov1 && (lo1 == 0) && (hi1 == CHUNK);
        bool p0  = ov0 && !f0;
        bool p1  = ov1 && !f1;

        unsigned mf0 = __ballot_sync(0xffffffffu, f0);
        unsigned mp0 = __ballot_sync(0xffffffffu, p0);
        unsigned mf1 = __ballot_sync(0xffffffffu, f1);
        unsigned mp1 = __ballot_sync(0xffffffffu, p1);
        int base = 0;
        if (lane == 0 && (mf0 | mp0 | mf1 | mp1))
            base = atomicAdd(&s_cnt,
                             ((__popc(mp0) + __popc(mp1)) << 16)
                             | (__popc(mf0) + __popc(mf1)));
        base = __shfl_sync(0xffffffffu, base, 0);
        int bF = base & 0xffff;
        int bP = base >> 16;
        int n0 = 2 * tid, n1 = 2 * tid + 1;
        if (f0) s_full[bF + __popc(mf0 & lt_mask)] = n0;
        if (f1) s_full[bF + __popc(mf0) + __popc(mf1 & lt_mask)] = n1;
        if (p0) s_part[bP + __popc(mp0 & lt_mask)]
                    = (n0 << 12) | (lo0 << 6) | hi0;
        if (p1) s_part[bP + __popc(mp0) + __popc(mp1 & lt_mask)]
                    = (n1 << 12) | (lo1 << 6) | hi1;
    }
    // Zero the diff array AFTER classify issues (needed only past barrier 2)
    ((float4*)&sdiff[0][0])[tid] = zero4;    // CHUNK*QB == 512
    __syncthreads();

    const int cnt   = s_cnt;
    const int nfull = cnt & 0xffff;
    const int npart = cnt >> 16;

    // ---- Partial nodes: 1 node/warp; sub0 adds at lo, sub1 subs at hi ---
    for (int p = g; p < npart; p += NGRP) {
        int pk = s_part[p];
        int n  = pk >> 12;
        int lo = (pk >> 6) & 63;
        int hi = pk & 63;
        float4 v = __ldg(&embed4[n * QUADS + qoff + qq]);
        if (sub == 0) {
            float* d = &sdiff[lo][qq].x;
            atomicAdd(d + 0, v.x);
            atomicAdd(d + 1, v.y);
            atomicAdd(d + 2, v.z);
            atomicAdd(d + 3, v.w);
        } else if (hi < CHUNK) {
            float* d = &sdiff[hi][qq].x;
            atomicAdd(d + 0, -v.x);
            atomicAdd(d + 1, -v.y);
            atomicAdd(d + 2, -v.z);
            atomicAdd(d + 3, -v.w);
        }
    }

    // ---- Full-cover nodes: 2 nodes/warp/iter, MLP=8 then residue --------
    {
        float4 a0 = zero4, a1 = zero4, a2 = zero4, a3 = zero4;
        int i = g * 2 + sub;                 // slot 0..31, stride 32
        for (; i + 224 < nfull; i += 256) {  // 8 entries in flight per slot
            int n0 = s_full[i];
            int n1 = s_full[i +  32];
            int n2 = s_full[i +  64];
            int n3 = s_full[i +  96];
            int n4 = s_full[i + 128];
            int n5 = s_full[i + 160];
            int n6 = s_full[i + 192];
            int n7 = s_full[i + 224];
            float4 v0 = __ldg(&embed4[n0 * QUADS + qoff + qq]);
            float4 v1 = __ldg(&embed4[n1 * QUADS + qoff + qq]);
            float4 v2 = __ldg(&embed4[n2 * QUADS + qoff + qq]);
            float4 v3 = __ldg(&embed4[n3 * QUADS + qoff + qq]);
            float4 v4 = __ldg(&embed4[n4 * QUADS + qoff + qq]);
            float4 v5 = __ldg(&embed4[n5 * QUADS + qoff + qq]);
            float4 v6 = __ldg(&embed4[n6 * QUADS + qoff + qq]);
            float4 v7 = __ldg(&embed4[n7 * QUADS + qoff + qq]);
            a0 = f4add(a0, f4add(v0, v4));
            a1 = f4add(a1, f4add(v1, v5));
            a2 = f4add(a2, f4add(v2, v6));
            a3 = f4add(a3, f4add(v3, v7));
        }
        for (; i + 96 < nfull; i += 128) {   // MLP=4 residue
            int n0 = s_full[i];
            int n1 = s_full[i + 32];
            int n2 = s_full[i + 64];
            int n3 = s_full[i + 96];
            a0 = f4add(a0, __ldg(&embed4[n0 * QUADS + qoff + qq]));
            a1 = f4add(a1, __ldg(&embed4[n1 * QUADS + qoff + qq]));
            a2 = f4add(a2, __ldg(&embed4[n2 * QUADS + qoff + qq]));
            a3 = f4add(a3, __ldg(&embed4[n3 * QUADS + qoff + qq]));
        }
        for (; i < nfull; i += 32)
            a0 = f4add(a0, __ldg(&embed4[s_full[i] * QUADS + qoff + qq]));
        float4 a = f4add(f4add(a0, a1), f4add(a2, a3));
        // fold the two node slots (sub 0/1) across half-warps
        a.x += __shfl_xor_sync(0xffffffffu, a.x, 16);
        a.y += __shfl_xor_sync(0xffffffffu, a.y, 16);
        a.z += __shfl_xor_sync(0xffffffffu, a.z, 16);
        a.w += __shfl_xor_sync(0xffffffffu, a.w, 16);
        if (sub == 0) gaccs[g][qq] = a;
    }
    __syncthreads();

    // ---- Phase B: role-split warps --------------------------------------
    if (g < 8) {                             // 2-token sums: entries 2g+sub
        int sidx = 2 * g + sub;
        sred[sidx][qq] = f4add(sdiff[2 * sidx][qq], sdiff[2 * sidx + 1][qq]);
    } else if (g < 10) {                     // 8-token sums: entries 2(g-8)+sub
        int a = 2 * (g - 8) + sub;
        float4 t0 = f4add(sdiff[8 * a + 0][qq], sdiff[8 * a + 1][qq]);
        float4 t1 = f4add(sdiff[8 * a + 2][qq], sdiff[8 * a + 3][qq]);
        float4 t2 = f4add(sdiff[8 * a + 4][qq], sdiff[8 * a + 5][qq]);
        float4 t3 = f4add(sdiff[8 * a + 6][qq], sdiff[8 * a + 7][qq]);
        ssup[a][qq] = f4add(f4add(t0, t1), f4add(t2, t3));
    } else if (g == 10) {                    // full-cover total: 8-deep + fold
        float4 a = zero4;
        #pragma unroll
        for (int r = 0; r < 8; ++r)
            a = f4add(a, gaccs[8 * sub + r][qq]);
        a.x += __shfl_xor_sync(0xffffffffu, a.x, 16);
        a.y += __shfl_xor_sync(0xffffffffu, a.y, 16);
        a.z += __shfl_xor_sync(0xffffffffu, a.z, 16);
        a.w += __shfl_xor_sync(0xffffffffu, a.w, 16);
        if (sub == 0) sfull[qq] = a;
    }
    __syncthreads();

    // ---- Phase C: scan, warp g owns tokens 2g and 2g+1 ------------------
    {
        const int a = g >> 2;                // 8-token groups before token 2g
        const int b = g & 3;                 // 2-token groups in current one
        float4 acc = sfull[qq];
        #pragma unroll
        for (int ss = 0; ss < 3; ++ss)
            if (ss < a) acc = f4add(acc, ssup[ss][qq]);
        #pragma unroll
        for (int j = 0; j < 3; ++j)
            if (j < b) acc = f4add(acc, sred[4 * a + j][qq]);
        acc = f4add(acc, sdiff[2 * g][qq]);
        out4[(c0 + 2 * g) * QUADS + qoff + qq] = acc;
        acc = f4add(acc, sdiff[2 * g + 1][qq]);
        out4[(c0 + 2 * g + 1) * QUADS + qoff + qq] = acc;
    }
}

extern "C" void kernel_launch(void* const* d_in, const int* in_sizes, int n_in,
                              void* d_out, int out_size) {
    const int2*   starts = (const int2*)d_in[0];
    const int2*   ends   = (const int2*)d_in[1];
    const float4* embed  = (const float4*)d_in[2];
    float4*       out    = (float4*)d_out;
    (void)in_sizes; (void)n_in; (void)out_size;
    span_encoder_kernel<<<NBLK, THREADS>>>(starts, ends, embed, out);
}